// round 2
// baseline (speedup 1.0000x reference)
#include <cuda_runtime.h>
#include <math.h>

#define TT   512
#define BB   64
#define EE   256
#define UU   512
#define G4U  2048
#define NCTA 128
#define NTHR 128

// -------- device scratch (static; no allocations) --------
__device__ float g_Y[(size_t)2 * TT * G4U * BB];   // [dir][t][n][b]
__device__ float g_h[2][2][UU][BB];                // [parity][dir][u][b]
__device__ unsigned g_bar_cnt;
__device__ unsigned g_bar_gen;

typedef unsigned long long ull;

__device__ __forceinline__ void fma2(ull& d, ull a, ull b) {
    asm("fma.rn.f32x2 %0, %1, %2, %0;" : "+l"(d) : "l"(a), "l"(b));
}
__device__ __forceinline__ ull splat(float x) {
    ull r; asm("mov.b64 %0, {%1, %1};" : "=l"(r) : "f"(x)); return r;
}
__device__ __forceinline__ float lo32(ull v) { return __uint_as_float((unsigned)v); }
__device__ __forceinline__ float hi32(ull v) { return __uint_as_float((unsigned)(v >> 32)); }
__device__ __forceinline__ float sigm(float x) { return 1.0f / (1.0f + expf(-x)); }

// -------- zero h state --------
__global__ void k_init() {
    int idx = blockIdx.x * blockDim.x + threadIdx.x;
    int n = gridDim.x * blockDim.x;
    float* h = &g_h[0][0][0][0];
    for (int i = idx; i < 2 * 2 * UU * BB; i += n) h[i] = 0.0f;
}

// -------- input projection (FFMA2): Y[dir][t][n][b] = emb[sent]@Wx + bias --------
__global__ __launch_bounds__(128) void k_xw(
    const int* __restrict__ sent, const float* __restrict__ emb,
    const float* __restrict__ Wxf, const float* __restrict__ bf,
    const float* __restrict__ Wxb, const float* __restrict__ bbv)
{
    int t  = blockIdx.x;           // 0..511
    int ny = blockIdx.y;           // 0..63
    int dir = ny >> 5;
    int n0  = (ny & 31) * 64;
    const float* Wx   = dir ? Wxb : Wxf;
    const float* bias = dir ? bbv : bf;
    float* Y = g_Y + ((size_t)dir * TT + t) * (size_t)(G4U * BB);

    __shared__ float As[64 * 68];    // [e][b], pad 68 -> float4 16B-aligned rows
    __shared__ float Bs[64 * 64];    // [e][n]
    __shared__ int   vrow[64];

    int tid = threadIdx.x;           // 128
    int tx = tid & 15, ty = tid >> 4;

    if (tid < 64) vrow[tid] = sent[tid * TT + t];
    __syncthreads();

    ull acc[4][4];                   // [b j][n-pair p]
    #pragma unroll
    for (int i = 0; i < 4; i++)
        #pragma unroll
        for (int j = 0; j < 4; j++) acc[i][j] = 0ull;

    for (int ec = 0; ec < EE; ec += 64) {
        {   // stage A (embedding gather)
            int b = tid & 63;
            int half = tid >> 6;
            const float* er = emb + (size_t)vrow[b] * EE + ec;
            #pragma unroll
            for (int j = 0; j < 8; j++) {
                int e4 = half + 2 * j;
                float4 v = *(const float4*)(er + 4 * e4);
                int e = 4 * e4;
                As[(e + 0) * 68 + b] = v.x;
                As[(e + 1) * 68 + b] = v.y;
                As[(e + 2) * 68 + b] = v.z;
                As[(e + 3) * 68 + b] = v.w;
            }
        }
        {   // stage B (weights)
            int n4 = tid & 15, er0 = tid >> 4;
            #pragma unroll
            for (int j = 0; j < 8; j++) {
                int e = er0 + 8 * j;
                float4 v = *(const float4*)(Wx + (size_t)(ec + e) * G4U + n0 + 4 * n4);
                *(float4*)(Bs + e * 64 + 4 * n4) = v;
            }
        }
        __syncthreads();
        #pragma unroll 8
        for (int k = 0; k < 64; k++) {
            float4 a = *(const float4*)(As + k * 68 + 4 * tx);
            ulonglong2 wA = *(const ulonglong2*)(Bs + k * 64 + 8 * ty);
            ulonglong2 wB = *(const ulonglong2*)(Bs + k * 64 + 8 * ty + 4);
            ull a0 = splat(a.x), a1 = splat(a.y), a2 = splat(a.z), a3 = splat(a.w);
            fma2(acc[0][0], a0, wA.x); fma2(acc[0][1], a0, wA.y);
            fma2(acc[0][2], a0, wB.x); fma2(acc[0][3], a0, wB.y);
            fma2(acc[1][0], a1, wA.x); fma2(acc[1][1], a1, wA.y);
            fma2(acc[1][2], a1, wB.x); fma2(acc[1][3], a1, wB.y);
            fma2(acc[2][0], a2, wA.x); fma2(acc[2][1], a2, wA.y);
            fma2(acc[2][2], a2, wB.x); fma2(acc[2][3], a2, wB.y);
            fma2(acc[3][0], a3, wA.x); fma2(acc[3][1], a3, wA.y);
            fma2(acc[3][2], a3, wB.x); fma2(acc[3][3], a3, wB.y);
        }
        __syncthreads();
    }
    #pragma unroll
    for (int p = 0; p < 4; p++) {
        int nn = n0 + 8 * ty + 2 * p;
        float bn0 = bias[nn], bn1 = bias[nn + 1];
        float4 o0 = make_float4(lo32(acc[0][p]) + bn0, lo32(acc[1][p]) + bn0,
                                lo32(acc[2][p]) + bn0, lo32(acc[3][p]) + bn0);
        float4 o1 = make_float4(hi32(acc[0][p]) + bn1, hi32(acc[1][p]) + bn1,
                                hi32(acc[2][p]) + bn1, hi32(acc[3][p]) + bn1);
        *(float4*)(Y + (size_t)nn * BB + 4 * tx) = o0;
        *(float4*)(Y + (size_t)(nn + 1) * BB + 4 * tx) = o1;
    }
}

// -------- grid-wide barrier (all CTAs resident by construction) --------
__device__ __forceinline__ void gsync() {
    __threadfence();
    __syncthreads();
    if (threadIdx.x == 0) {
        unsigned g = *(volatile unsigned*)&g_bar_gen;
        unsigned a = atomicAdd(&g_bar_cnt, 1u);
        if (a == NCTA - 1) {
            g_bar_cnt = 0;
            __threadfence();
            *(volatile unsigned*)&g_bar_gen = g + 1;
        } else {
            while (*(volatile unsigned*)&g_bar_gen == g) {}
            __threadfence();
        }
    }
    __syncthreads();
}

// -------- persistent recurrent kernel: 128 CTAs, each = 1 dir x 8 hidden units --------
__global__ __launch_bounds__(NTHR, 1) void k_rec(
    const float* __restrict__ Whf, const float* __restrict__ Whb)
{
    extern __shared__ float sm[];
    float* ws  = sm;                 // [512][32]  weight slice (k-major)  64 KB
    float* hs2 = ws + 512 * 32;      // 2 x [64][128]  h chunk, b-duplicated  64 KB
    float* zs  = hs2 + 2 * 64 * 128; // [32][64]  z tile  8 KB
    float* cs  = zs + 32 * 64;       // [8][64]  cell state (persistent)  2 KB

    int tid = threadIdx.x;
    int dir = blockIdx.x >> 6;
    int u0  = (blockIdx.x & 63) << 3;
    const float* Wh = dir ? Whb : Whf;

    // load + transpose Wh slice once: ws[k*32+lc], lc -> n = (lc>>3)*U + u0 + (lc&7)
    for (int idx = tid; idx < 512 * 32; idx += NTHR) {
        int k = idx >> 5, lc = idx & 31;
        int n = ((lc >> 3) * UU) + u0 + (lc & 7);
        ws[idx] = Wh[(size_t)k * G4U + n];
    }
    for (int i = tid; i < 8 * 64; i += NTHR) cs[i] = 0.0f;
    __syncthreads();

    int lane = tid & 31, warp = tid >> 5;
    int colg = lane & 7;                    // 8 column-groups of 4
    int b0   = warp * 16 + (lane >> 3) * 4; // 4 batches per thread
    const float* Ybase = g_Y + (size_t)dir * TT * (size_t)(G4U * BB);

    for (int t = 0; t < TT; t++) {
        const float* hin = &g_h[t & 1][dir][0][0];

        // stage chunk 0 (duplicated over b for f32x2 splats)
        float4 pre[8];
        #pragma unroll
        for (int j = 0; j < 8; j++)
            pre[j] = __ldcg((const float4*)hin + tid + 128 * j);
        #pragma unroll
        for (int j = 0; j < 8; j++) {
            int idx = tid + 128 * j;
            int kl = idx >> 4, bq = idx & 15;
            float2* r = (float2*)(hs2 + kl * 128) + bq * 4;
            r[0] = make_float2(pre[j].x, pre[j].x);
            r[1] = make_float2(pre[j].y, pre[j].y);
            r[2] = make_float2(pre[j].z, pre[j].z);
            r[3] = make_float2(pre[j].w, pre[j].w);
        }
        __syncthreads();

        ull acc[8];
        #pragma unroll
        for (int i = 0; i < 8; i++) acc[i] = 0ull;

        for (int c = 0; c < 8; c++) {
            if (c < 7) {
                const float4* src = (const float4*)(hin + (c + 1) * 64 * 64);
                #pragma unroll
                for (int j = 0; j < 8; j++) pre[j] = __ldcg(src + tid + 128 * j);
            }
            const float* wrow = ws + (c * 64) * 32 + 4 * colg;
            const float* hrow = hs2 + (c & 1) * (64 * 128) + 2 * b0;
            #pragma unroll 8
            for (int k = 0; k < 64; k++) {
                ulonglong2 wv = *(const ulonglong2*)(wrow + k * 32);
                ulonglong2 hA = *(const ulonglong2*)(hrow + k * 128);
                ulonglong2 hB = *(const ulonglong2*)(hrow + k * 128 + 4);
                fma2(acc[0], hA.x, wv.x); fma2(acc[1], hA.x, wv.y);
                fma2(acc[2], hA.y, wv.x); fma2(acc[3], hA.y, wv.y);
                fma2(acc[4], hB.x, wv.x); fma2(acc[5], hB.x, wv.y);
                fma2(acc[6], hB.y, wv.x); fma2(acc[7], hB.y, wv.y);
            }
            __syncthreads();
            if (c < 7) {
                float* nb = hs2 + ((c + 1) & 1) * (64 * 128);
                #pragma unroll
                for (int j = 0; j < 8; j++) {
                    int idx = tid + 128 * j;
                    int kl = idx >> 4, bq = idx & 15;
                    float2* r = (float2*)(nb + kl * 128) + bq * 4;
                    r[0] = make_float2(pre[j].x, pre[j].x);
                    r[1] = make_float2(pre[j].y, pre[j].y);
                    r[2] = make_float2(pre[j].z, pre[j].z);
                    r[3] = make_float2(pre[j].w, pre[j].w);
                }
                __syncthreads();
            }
        }

        // scatter z to SMEM: zs[lc][b]
        #pragma unroll
        for (int j = 0; j < 4; j++) {
            ull a0 = acc[2 * j], a1 = acc[2 * j + 1];
            zs[(4 * colg + 0) * 64 + b0 + j] = lo32(a0);
            zs[(4 * colg + 1) * 64 + b0 + j] = hi32(a0);
            zs[(4 * colg + 2) * 64 + b0 + j] = lo32(a1);
            zs[(4 * colg + 3) * 64 + b0 + j] = hi32(a1);
        }
        __syncthreads();

        // cell update: thread -> (du, 4 batches)
        int tt = dir ? (TT - 1 - t) : t;
        const float* Yt = Ybase + (size_t)tt * (size_t)(G4U * BB);
        float* hout = &g_h[(t + 1) & 1][dir][0][0];
        int du = tid >> 4;
        int be = (tid & 15) * 4;
        int u = u0 + du;
        float4 z0 = *(const float4*)(zs + (0 * 8 + du) * 64 + be);
        float4 z1 = *(const float4*)(zs + (1 * 8 + du) * 64 + be);
        float4 z2 = *(const float4*)(zs + (2 * 8 + du) * 64 + be);
        float4 z3 = *(const float4*)(zs + (3 * 8 + du) * 64 + be);
        float4 y0 = *(const float4*)(Yt + (size_t)(0 * UU + u) * BB + be);
        float4 y1 = *(const float4*)(Yt + (size_t)(1 * UU + u) * BB + be);
        float4 y2 = *(const float4*)(Yt + (size_t)(2 * UU + u) * BB + be);
        float4 y3 = *(const float4*)(Yt + (size_t)(3 * UU + u) * BB + be);
        float4 cc = *(float4*)(cs + du * 64 + be);
        float4 cn, hn;
        cn.x = sigm(z1.x + y1.x) * cc.x + sigm(z0.x + y0.x) * tanhf(z2.x + y2.x);
        cn.y = sigm(z1.y + y1.y) * cc.y + sigm(z0.y + y0.y) * tanhf(z2.y + y2.y);
        cn.z = sigm(z1.z + y1.z) * cc.z + sigm(z0.z + y0.z) * tanhf(z2.z + y2.z);
        cn.w = sigm(z1.w + y1.w) * cc.w + sigm(z0.w + y0.w) * tanhf(z2.w + y2.w);
        hn.x = sigm(z3.x + y3.x) * tanhf(cn.x);
        hn.y = sigm(z3.y + y3.y) * tanhf(cn.y);
        hn.z = sigm(z3.z + y3.z) * tanhf(cn.z);
        hn.w = sigm(z3.w + y3.w) * tanhf(cn.w);
        *(float4*)(cs + du * 64 + be) = cn;
        *(float4*)(hout + (size_t)u * BB + be) = hn;

        gsync();
    }
}

// -------- head: out[b] = sigmoid( (h@W1+b1) @ W2 + b2 ) --------
__global__ void k_head(const float* __restrict__ W1, const float* __restrict__ b1,
                       const float* __restrict__ W2, const float* __restrict__ b2,
                       float* __restrict__ out)
{
    int b = blockIdx.x;     // 64
    int j = threadIdx.x;    // 64
    const float* hf = &g_h[0][0][0][0];
    const float* hb = &g_h[0][1][0][0];
    float s = b1[j];
    #pragma unroll 4
    for (int k = 0; k < UU; k++) s += hf[k * 64 + b] * W1[(size_t)k * 64 + j];
    #pragma unroll 4
    for (int k = 0; k < UU; k++) s += hb[k * 64 + b] * W1[(size_t)(UU + k) * 64 + j];
    float v = s * W2[j];
    __shared__ float red[64];
    red[j] = v;
    __syncthreads();
    for (int st = 32; st > 0; st >>= 1) {
        if (j < st) red[j] += red[j + st];
        __syncthreads();
    }
    if (j == 0) out[b] = sigm(red[0] + b2[0]);
}

extern "C" void kernel_launch(void* const* d_in, const int* in_sizes, int n_in,
                              void* d_out, int out_size)
{
    const int*   sent = (const int*)  d_in[0];
    const float* emb  = (const float*)d_in[1];
    const float* Wxf  = (const float*)d_in[2];
    const float* Whf  = (const float*)d_in[3];
    const float* bf   = (const float*)d_in[4];
    const float* Wxb  = (const float*)d_in[5];
    const float* Whb  = (const float*)d_in[6];
    const float* bbv  = (const float*)d_in[7];
    const float* W1   = (const float*)d_in[8];
    const float* b1   = (const float*)d_in[9];
    const float* W2   = (const float*)d_in[10];
    const float* b2   = (const float*)d_in[11];
    float* out = (float*)d_out;

    const int smem = (512 * 32 + 2 * 64 * 128 + 32 * 64 + 8 * 64) * 4;  // 141312 B
    cudaFuncSetAttribute(k_rec, cudaFuncAttributeMaxDynamicSharedMemorySize, smem);

    k_init<<<256, 256>>>();
    k_xw<<<dim3(TT, 64), 128>>>(sent, emb, Wxf, bf, Wxb, bbv);
    k_rec<<<NCTA, NTHR, smem>>>(Whf, Whb);
    k_head<<<64, 64>>>(W1, b1, W2, b2, out);
}

// round 3
// speedup vs baseline: 1.2035x; 1.2035x over previous
#include <cuda_runtime.h>
#include <math.h>

#define TT   512
#define BB   64
#define EE   256
#define UU   512
#define G4U  2048
#define NCTA 128   // 64 per direction
#define NTHR 256

// -------- device scratch (static; no allocations) --------
__device__ float g_Y[(size_t)2 * TT * G4U * BB];   // [dir][t][n][b]
__device__ float g_h[2][2][UU][BB];                // [parity][dir][u][b]
__device__ unsigned g_cnt[2][32];                  // per-dir barrier (padded)
__device__ unsigned g_gen[2][32];

typedef unsigned long long ull;

__device__ __forceinline__ void fma2(ull& d, ull a, ull b) {
    asm("fma.rn.f32x2 %0, %1, %2, %0;" : "+l"(d) : "l"(a), "l"(b));
}
__device__ __forceinline__ ull splat(float x) {
    ull r; asm("mov.b64 %0, {%1, %1};" : "=l"(r) : "f"(x)); return r;
}
__device__ __forceinline__ float lo32(ull v) { return __uint_as_float((unsigned)v); }
__device__ __forceinline__ float hi32(ull v) { return __uint_as_float((unsigned)(v >> 32)); }
__device__ __forceinline__ float sigm(float x) { return 1.0f / (1.0f + expf(-x)); }

// -------- input projection (FFMA2): Y[dir][t][n][b] = emb[sent]@Wx + bias --------
__global__ __launch_bounds__(128) void k_xw(
    const int* __restrict__ sent, const float* __restrict__ emb,
    const float* __restrict__ Wxf, const float* __restrict__ bf,
    const float* __restrict__ Wxb, const float* __restrict__ bbv)
{
    int t  = blockIdx.x;
    int ny = blockIdx.y;
    int dir = ny >> 5;
    int n0  = (ny & 31) * 64;
    const float* Wx   = dir ? Wxb : Wxf;
    const float* bias = dir ? bbv : bf;
    float* Y = g_Y + ((size_t)dir * TT + t) * (size_t)(G4U * BB);

    __shared__ float As[64 * 68];
    __shared__ float Bs[64 * 64];
    __shared__ int   vrow[64];

    int tid = threadIdx.x;
    int tx = tid & 15, ty = tid >> 4;

    if (tid < 64) vrow[tid] = sent[tid * TT + t];
    __syncthreads();

    ull acc[4][4];
    #pragma unroll
    for (int i = 0; i < 4; i++)
        #pragma unroll
        for (int j = 0; j < 4; j++) acc[i][j] = 0ull;

    for (int ec = 0; ec < EE; ec += 64) {
        {
            int b = tid & 63;
            int half = tid >> 6;
            const float* er = emb + (size_t)vrow[b] * EE + ec;
            #pragma unroll
            for (int j = 0; j < 8; j++) {
                int e4 = half + 2 * j;
                float4 v = *(const float4*)(er + 4 * e4);
                int e = 4 * e4;
                As[(e + 0) * 68 + b] = v.x;
                As[(e + 1) * 68 + b] = v.y;
                As[(e + 2) * 68 + b] = v.z;
                As[(e + 3) * 68 + b] = v.w;
            }
        }
        {
            int n4 = tid & 15, er0 = tid >> 4;
            #pragma unroll
            for (int j = 0; j < 8; j++) {
                int e = er0 + 8 * j;
                float4 v = *(const float4*)(Wx + (size_t)(ec + e) * G4U + n0 + 4 * n4);
                *(float4*)(Bs + e * 64 + 4 * n4) = v;
            }
        }
        __syncthreads();
        #pragma unroll 8
        for (int k = 0; k < 64; k++) {
            float4 a = *(const float4*)(As + k * 68 + 4 * tx);
            ulonglong2 wA = *(const ulonglong2*)(Bs + k * 64 + 8 * ty);
            ulonglong2 wB = *(const ulonglong2*)(Bs + k * 64 + 8 * ty + 4);
            ull a0 = splat(a.x), a1 = splat(a.y), a2 = splat(a.z), a3 = splat(a.w);
            fma2(acc[0][0], a0, wA.x); fma2(acc[0][1], a0, wA.y);
            fma2(acc[0][2], a0, wB.x); fma2(acc[0][3], a0, wB.y);
            fma2(acc[1][0], a1, wA.x); fma2(acc[1][1], a1, wA.y);
            fma2(acc[1][2], a1, wB.x); fma2(acc[1][3], a1, wB.y);
            fma2(acc[2][0], a2, wA.x); fma2(acc[2][1], a2, wA.y);
            fma2(acc[2][2], a2, wB.x); fma2(acc[2][3], a2, wB.y);
            fma2(acc[3][0], a3, wA.x); fma2(acc[3][1], a3, wA.y);
            fma2(acc[3][2], a3, wB.x); fma2(acc[3][3], a3, wB.y);
        }
        __syncthreads();
    }
    #pragma unroll
    for (int p = 0; p < 4; p++) {
        int nn = n0 + 8 * ty + 2 * p;
        float bn0 = bias[nn], bn1 = bias[nn + 1];
        float4 o0 = make_float4(lo32(acc[0][p]) + bn0, lo32(acc[1][p]) + bn0,
                                lo32(acc[2][p]) + bn0, lo32(acc[3][p]) + bn0);
        float4 o1 = make_float4(hi32(acc[0][p]) + bn1, hi32(acc[1][p]) + bn1,
                                hi32(acc[2][p]) + bn1, hi32(acc[3][p]) + bn1);
        *(float4*)(Y + (size_t)nn * BB + 4 * tx) = o0;
        *(float4*)(Y + (size_t)(nn + 1) * BB + 4 * tx) = o1;
    }
}

// -------- per-direction barrier over 64 CTAs (all resident by construction) --------
__device__ __forceinline__ void gsync(int dir) {
    __threadfence();
    __syncthreads();
    if (threadIdx.x == 0) {
        volatile unsigned* gen = &g_gen[dir][0];
        unsigned g = *gen;
        unsigned a = atomicAdd(&g_cnt[dir][0], 1u);
        if (a == 63) {
            g_cnt[dir][0] = 0;
            __threadfence();
            *gen = g + 1;
        } else {
            while (*gen == g) {}
            __threadfence();
        }
    }
    __syncthreads();
}

// -------- persistent recurrent kernel: 128 CTAs x 256 thr, CTA = 1 dir x 8 units --------
__global__ __launch_bounds__(NTHR, 1) void k_rec(
    const float* __restrict__ Whf, const float* __restrict__ Whb)
{
    extern __shared__ float sm[];
    float* wsd = sm;                  // [512][64] duplicated weight slice  128 KB
    float* hs  = wsd + 512 * 64;      // 2 x [128][64] h chunk              64 KB
    float* zs2 = hs + 2 * 128 * 64;   // [2][32][64] partial z              16 KB
    float* cs  = zs2 + 2 * 32 * 64;   // [8][64] cell state                  2 KB

    int tid = threadIdx.x;
    int dir = blockIdx.x >> 6;
    int u0  = (blockIdx.x & 63) << 3;
    const float* Wh = dir ? Whb : Whf;

    // fill duplicated weight slice once: wsd[k][2*lc+{0,1}] = Wh[k][n(lc)]
    for (int idx = tid; idx < 512 * 64; idx += NTHR) {
        int k = idx >> 6, q = idx & 63;
        int lc = q >> 1;
        int n = ((lc >> 3) * UU) + u0 + (lc & 7);
        wsd[idx] = Wh[(size_t)k * G4U + n];
    }
    for (int i = tid; i < 8 * 64; i += NTHR) cs[i] = 0.0f;
    __syncthreads();

    // GEMM mapping: kg = k-group, cp = col-pair (16), bg = batch-group of 8
    int kg = tid >> 7;
    int pos = tid & 127;
    int cp = pos >> 3;
    int b0 = (pos & 7) * 8;

    // epilogue mapping
    int du = tid >> 5;
    int be = (tid & 31) * 2;
    int u  = u0 + du;

    const float* Ybase = g_Y + (size_t)dir * TT * (size_t)(G4U * BB);

    for (int t = 0; t < TT; t++) {
        // prefetch Y for this step (epilogue operands)
        int tt = dir ? (TT - 1 - t) : t;
        const float* Yt = Ybase + (size_t)tt * (size_t)(G4U * BB);
        float2 yv[4];
        #pragma unroll
        for (int gate = 0; gate < 4; gate++)
            yv[gate] = __ldcg((const float2*)(Yt + (size_t)(gate * UU + u) * BB + be));

        ull acc[2][4];
        #pragma unroll
        for (int c = 0; c < 2; c++)
            #pragma unroll
            for (int j = 0; j < 4; j++) acc[c][j] = 0ull;

        if (t > 0) {
            const float* hin = &g_h[t & 1][dir][0][0];
            float4 p[8];
            // stage chunk 0
            #pragma unroll
            for (int j = 0; j < 8; j++)
                p[j] = __ldcg((const float4*)hin + tid + 256 * j);
            #pragma unroll
            for (int j = 0; j < 8; j++)
                ((float4*)hs)[tid + 256 * j] = p[j];
            __syncthreads();

            for (int c = 0; c < 4; c++) {
                if (c < 3) {
                    const float4* src = (const float4*)hin + (c + 1) * 2048;
                    #pragma unroll
                    for (int j = 0; j < 8; j++) p[j] = __ldcg(src + tid + 256 * j);
                }
                const float* hrow = hs + (c & 1) * 8192 + (kg * 64) * 64 + b0;
                const float* wrow = wsd + (c * 128 + kg * 64) * 64 + 4 * cp;
                #pragma unroll 8
                for (int k = 0; k < 64; k++) {
                    ulonglong2 wq = *(const ulonglong2*)(wrow + k * 64);
                    ulonglong2 h1 = *(const ulonglong2*)(hrow + k * 64);
                    ulonglong2 h2 = *(const ulonglong2*)(hrow + k * 64 + 4);
                    fma2(acc[0][0], h1.x, wq.x); fma2(acc[0][1], h1.y, wq.x);
                    fma2(acc[0][2], h2.x, wq.x); fma2(acc[0][3], h2.y, wq.x);
                    fma2(acc[1][0], h1.x, wq.y); fma2(acc[1][1], h1.y, wq.y);
                    fma2(acc[1][2], h2.x, wq.y); fma2(acc[1][3], h2.y, wq.y);
                }
                if (c < 3) {
                    __syncthreads();   // done reading buf (c&1); safe to fill other buf next? (fills buf (c+1)&1)
                    float4* dst = (float4*)(hs + ((c + 1) & 1) * 8192);
                    #pragma unroll
                    for (int j = 0; j < 8; j++) dst[tid + 256 * j] = p[j];
                    __syncthreads();
                }
            }
        }

        // write partial z
        {
            float* zp = zs2 + ((kg * 32) + 2 * cp) * 64 + b0;
            *(ull*)(zp + 0) = acc[0][0]; *(ull*)(zp + 2) = acc[0][1];
            *(ull*)(zp + 4) = acc[0][2]; *(ull*)(zp + 6) = acc[0][3];
            zp += 64;
            *(ull*)(zp + 0) = acc[1][0]; *(ull*)(zp + 2) = acc[1][1];
            *(ull*)(zp + 4) = acc[1][2]; *(ull*)(zp + 6) = acc[1][3];
        }
        __syncthreads();

        // cell update (reduce the two k-groups inline)
        {
            float* hout = &g_h[(t + 1) & 1][dir][0][0];
            float2 z[4];
            #pragma unroll
            for (int gate = 0; gate < 4; gate++) {
                int lc = gate * 8 + du;
                float2 a = *(const float2*)(zs2 + lc * 64 + be);
                float2 bpart = *(const float2*)(zs2 + (32 + lc) * 64 + be);
                z[gate] = make_float2(a.x + bpart.x + yv[gate].x,
                                      a.y + bpart.y + yv[gate].y);
            }
            float2 cc = *(float2*)(cs + du * 64 + be);
            float2 cn, hn;
            cn.x = sigm(z[1].x) * cc.x + sigm(z[0].x) * tanhf(z[2].x);
            cn.y = sigm(z[1].y) * cc.y + sigm(z[0].y) * tanhf(z[2].y);
            hn.x = sigm(z[3].x) * tanhf(cn.x);
            hn.y = sigm(z[3].y) * tanhf(cn.y);
            *(float2*)(cs + du * 64 + be) = cn;
            *(float2*)(hout + (size_t)u * BB + be) = hn;
        }
        __syncthreads();   // zs2 reuse guard

        if (t < TT - 1) gsync(dir);
    }
}

// -------- head: out[b] = sigmoid( (h@W1+b1) @ W2 + b2 ) --------
__global__ __launch_bounds__(256) void k_head(
    const float* __restrict__ W1, const float* __restrict__ b1,
    const float* __restrict__ W2, const float* __restrict__ b2,
    float* __restrict__ out)
{
    int b = blockIdx.x;      // 64
    int tid = threadIdx.x;   // 256
    int j = tid & 63, kq = tid >> 6;
    const float* h = &g_h[0][0][0][0];   // [2][512][64] -> k = dir*512+u
    float s = 0.0f;
    #pragma unroll 4
    for (int k = kq * 256; k < kq * 256 + 256; k++)
        s += h[k * 64 + b] * W1[(size_t)k * 64 + j];
    __shared__ float red[4][64];
    red[kq][j] = s;
    __syncthreads();
    if (tid < 64) {
        float sj = red[0][j] + red[1][j] + red[2][j] + red[3][j] + b1[j];
        red[0][j] = sj * W2[j];
    }
    __syncthreads();
    if (tid == 0) {
        float v = 0.0f;
        #pragma unroll
        for (int q = 0; q < 64; q++) v += red[0][q];
        out[b] = sigm(v + b2[0]);
    }
}

extern "C" void kernel_launch(void* const* d_in, const int* in_sizes, int n_in,
                              void* d_out, int out_size)
{
    const int*   sent = (const int*)  d_in[0];
    const float* emb  = (const float*)d_in[1];
    const float* Wxf  = (const float*)d_in[2];
    const float* Whf  = (const float*)d_in[3];
    const float* bf   = (const float*)d_in[4];
    const float* Wxb  = (const float*)d_in[5];
    const float* Whb  = (const float*)d_in[6];
    const float* bbv  = (const float*)d_in[7];
    const float* W1   = (const float*)d_in[8];
    const float* b1   = (const float*)d_in[9];
    const float* W2   = (const float*)d_in[10];
    const float* b2   = (const float*)d_in[11];
    float* out = (float*)d_out;

    const int smem = (512 * 64 + 2 * 128 * 64 + 2 * 32 * 64 + 8 * 64) * 4;  // 215040 B
    cudaFuncSetAttribute(k_rec, cudaFuncAttributeMaxDynamicSharedMemorySize, smem);

    k_xw<<<dim3(TT, 64), 128>>>(sent, emb, Wxf, bf, Wxb, bbv);
    k_rec<<<NCTA, NTHR, smem>>>(Whf, Whb);
    k_head<<<64, 256>>>(W1, b1, W2, b2, out);
}

// round 6
// speedup vs baseline: 2.7576x; 2.2914x over previous
#include <cuda_runtime.h>
#include <cuda_bf16.h>
#include <math.h>
#include <stdint.h>

#define TT   512
#define BB   64
#define EE   256
#define UU   512
#define G4U  2048
#define NCTA 128   // 64 per direction
#define NTHR 256
#define ZST  34    // zbuf row stride (floats); even -> float2-aligned rows

// -------- device scratch --------
__device__ __align__(16) float g_Y[(size_t)2 * TT * G4U * BB];   // [dir][t][n][b]
__device__ __align__(16) __nv_bfloat16 g_hT[2][2][2][BB][UU];    // [parity][split][dir][b][u]
__device__ unsigned g_cnt[2][32];
__device__ unsigned g_gen[2][32];

typedef unsigned long long ull;

__device__ __forceinline__ void fma2(ull& d, ull a, ull b) {
    asm("fma.rn.f32x2 %0, %1, %2, %0;" : "+l"(d) : "l"(a), "l"(b));
}
__device__ __forceinline__ ull splat(float x) {
    ull r; asm("mov.b64 %0, {%1, %1};" : "=l"(r) : "f"(x)); return r;
}
__device__ __forceinline__ float lo32(ull v) { return __uint_as_float((unsigned)v); }
__device__ __forceinline__ float hi32(ull v) { return __uint_as_float((unsigned)(v >> 32)); }
__device__ __forceinline__ float sigm(float x) { return 1.0f / (1.0f + expf(-x)); }

__device__ __forceinline__ uint32_t smem_u32(const void* p) {
    uint32_t a;
    asm("{ .reg .u64 t; cvta.to.shared.u64 t, %1; cvt.u32.u64 %0, t; }" : "=r"(a) : "l"(p));
    return a;
}
__device__ __forceinline__ void ldm4(uint32_t* r, uint32_t addr) {
    asm volatile("ldmatrix.sync.aligned.m8n8.x4.shared.b16 {%0,%1,%2,%3}, [%4];"
                 : "=r"(r[0]), "=r"(r[1]), "=r"(r[2]), "=r"(r[3]) : "r"(addr));
}
__device__ __forceinline__ void mma16816(float* d, const uint32_t* a, uint32_t b0, uint32_t b1) {
    asm volatile("mma.sync.aligned.m16n8k16.row.col.f32.bf16.bf16.f32 "
                 "{%0,%1,%2,%3}, {%4,%5,%6,%7}, {%8,%9}, {%0,%1,%2,%3};"
                 : "+f"(d[0]), "+f"(d[1]), "+f"(d[2]), "+f"(d[3])
                 : "r"(a[0]), "r"(a[1]), "r"(a[2]), "r"(a[3]), "r"(b0), "r"(b1));
}

// -------- init: zero hT --------
__global__ void k_init() {
    int idx = blockIdx.x * blockDim.x + threadIdx.x;
    int n = gridDim.x * blockDim.x;
    uint4* p = (uint4*)&g_hT[0][0][0][0][0];
    const int total = 2 * 2 * 2 * BB * UU * 2 / 16;
    for (int i = idx; i < total; i += n) p[i] = make_uint4(0, 0, 0, 0);
}

// -------- input projection (FFMA2, unchanged) --------
__global__ __launch_bounds__(128) void k_xw(
    const int* __restrict__ sent, const float* __restrict__ emb,
    const float* __restrict__ Wxf, const float* __restrict__ bf,
    const float* __restrict__ Wxb, const float* __restrict__ bbv)
{
    int t  = blockIdx.x;
    int ny = blockIdx.y;
    int dir = ny >> 5;
    int n0  = (ny & 31) * 64;
    const float* Wx   = dir ? Wxb : Wxf;
    const float* bias = dir ? bbv : bf;
    float* Y = g_Y + ((size_t)dir * TT + t) * (size_t)(G4U * BB);

    __shared__ float As[64 * 68];
    __shared__ float Bs[64 * 64];
    __shared__ int   vrow[64];

    int tid = threadIdx.x;
    int tx = tid & 15, ty = tid >> 4;

    if (tid < 64) vrow[tid] = sent[tid * TT + t];
    __syncthreads();

    ull acc[4][4];
    #pragma unroll
    for (int i = 0; i < 4; i++)
        #pragma unroll
        for (int j = 0; j < 4; j++) acc[i][j] = 0ull;

    for (int ec = 0; ec < EE; ec += 64) {
        {
            int b = tid & 63;
            int half = tid >> 6;
            const float* er = emb + (size_t)vrow[b] * EE + ec;
            #pragma unroll
            for (int j = 0; j < 8; j++) {
                int e4 = half + 2 * j;
                float4 v = *(const float4*)(er + 4 * e4);
                int e = 4 * e4;
                As[(e + 0) * 68 + b] = v.x;
                As[(e + 1) * 68 + b] = v.y;
                As[(e + 2) * 68 + b] = v.z;
                As[(e + 3) * 68 + b] = v.w;
            }
        }
        {
            int n4 = tid & 15, er0 = tid >> 4;
            #pragma unroll
            for (int j = 0; j < 8; j++) {
                int e = er0 + 8 * j;
                float4 v = *(const float4*)(Wx + (size_t)(ec + e) * G4U + n0 + 4 * n4);
                *(float4*)(Bs + e * 64 + 4 * n4) = v;
            }
        }
        __syncthreads();
        #pragma unroll 8
        for (int k = 0; k < 64; k++) {
            float4 a = *(const float4*)(As + k * 68 + 4 * tx);
            ulonglong2 wA = *(const ulonglong2*)(Bs + k * 64 + 8 * ty);
            ulonglong2 wB = *(const ulonglong2*)(Bs + k * 64 + 8 * ty + 4);
            ull a0 = splat(a.x), a1 = splat(a.y), a2 = splat(a.z), a3 = splat(a.w);
            fma2(acc[0][0], a0, wA.x); fma2(acc[0][1], a0, wA.y);
            fma2(acc[0][2], a0, wB.x); fma2(acc[0][3], a0, wB.y);
            fma2(acc[1][0], a1, wA.x); fma2(acc[1][1], a1, wA.y);
            fma2(acc[1][2], a1, wB.x); fma2(acc[1][3], a1, wB.y);
            fma2(acc[2][0], a2, wA.x); fma2(acc[2][1], a2, wA.y);
            fma2(acc[2][2], a2, wB.x); fma2(acc[2][3], a2, wB.y);
            fma2(acc[3][0], a3, wA.x); fma2(acc[3][1], a3, wA.y);
            fma2(acc[3][2], a3, wB.x); fma2(acc[3][3], a3, wB.y);
        }
        __syncthreads();
    }
    #pragma unroll
    for (int p = 0; p < 4; p++) {
        int nn = n0 + 8 * ty + 2 * p;
        float bn0 = bias[nn], bn1 = bias[nn + 1];
        float4 o0 = make_float4(lo32(acc[0][p]) + bn0, lo32(acc[1][p]) + bn0,
                                lo32(acc[2][p]) + bn0, lo32(acc[3][p]) + bn0);
        float4 o1 = make_float4(hi32(acc[0][p]) + bn1, hi32(acc[1][p]) + bn1,
                                hi32(acc[2][p]) + bn1, hi32(acc[3][p]) + bn1);
        *(float4*)(Y + (size_t)nn * BB + 4 * tx) = o0;
        *(float4*)(Y + (size_t)(nn + 1) * BB + 4 * tx) = o1;
    }
}

// -------- per-direction barrier over 64 CTAs --------
__device__ __forceinline__ void gsync(int dir) {
    __threadfence();
    __syncthreads();
    if (threadIdx.x == 0) {
        volatile unsigned* gen = &g_gen[dir][0];
        unsigned g = *gen;
        unsigned a = atomicAdd(&g_cnt[dir][0], 1u);
        if (a == 63) {
            g_cnt[dir][0] = 0;
            __threadfence();
            *gen = g + 1;
        } else {
            while (*gen == g) {}
            __threadfence();
        }
    }
    __syncthreads();
}

// -------- persistent HMMA recurrence: 128 CTAs x 256 thr; CTA = 1 dir x 8 units --------
__global__ __launch_bounds__(NTHR, 1) void k_rec(
    const float* __restrict__ Whf, const float* __restrict__ Whb)
{
    extern __shared__ char dsm[];
    char* smA  = dsm;                        // 131072 B
    char* smB  = dsm + 131072;               // 65536 B
    float* zbuf = (float*)(dsm + 131072 + 65536);   // 8*32*ZST fp32
    __nv_bfloat16* hstage = (__nv_bfloat16*)smA;    // 2 KB, reused between phases

    int tid = threadIdx.x, lane = tid & 31, w = tid >> 5;
    int dir = blockIdx.x >> 6;
    int u0  = (blockIdx.x & 63) * 8;
    const float* Wh = dir ? Whb : Whf;

    // ---- build B once: rows 0-31 = W_hi, 32-63 = W_lo; swizzled 16B chunks
    for (int idx = tid; idx < 64 * 512; idx += NTHR) {
        int n = idx >> 9, k = idx & 511;
        int nl = n & 31;
        float wv = Wh[(size_t)k * G4U + ((nl >> 3) * UU + u0 + (nl & 7))];
        __nv_bfloat16 hi = __float2bfloat16(wv);
        __nv_bfloat16 v = (n < 32) ? hi : __float2bfloat16(wv - __bfloat162float(hi));
        uint32_t off = (uint32_t)(n * 1024 + ((((k >> 3) ^ (n & 7))) << 4) + (k & 7) * 2);
        *(__nv_bfloat16*)(smB + off) = v;
    }

    // ---- per-lane ldmatrix address precompute
    uint32_t smA32 = smem_u32(smA), smB32 = smem_u32(smB);
    int mg = w >> 1, ng = w & 1;
    uint32_t aBase[2], bBase[2], aSw[2][4], bSw[2][4];
    {
        int dA = (lane >> 4) & 1;
        #pragma unroll
        for (int mt = 0; mt < 2; mt++) {
            int row = mg * 32 + mt * 16 + ((lane >> 3) & 1) * 8 + (lane & 7);
            aBase[mt] = smA32 + row * 1024;
            #pragma unroll
            for (int j = 0; j < 4; j++)
                aSw[mt][j] = (uint32_t)(((2 * j + dA) ^ (row & 7)) << 4);
        }
        int dB = (lane >> 3) & 1;
        #pragma unroll
        for (int nt = 0; nt < 2; nt++) {
            int row = ng * 32 + nt * 16 + ((lane >> 4) & 1) * 8 + (lane & 7);
            bBase[nt] = smB32 + row * 1024;
            #pragma unroll
            for (int j = 0; j < 4; j++)
                bSw[nt][j] = (uint32_t)(((2 * j + dB) ^ (row & 7)) << 4);
        }
    }

    int b = tid & 63, du0 = tid >> 6;
    float creg[2] = {0.0f, 0.0f};
    const float* Ybase = g_Y + (size_t)dir * TT * (size_t)(G4U * BB);
    __syncthreads();

    for (int t = 0; t < TT; t++) {
        // Y prefetch for this thread's 2 cells
        int ttv = dir ? (TT - 1 - t) : t;
        const float* Yt = Ybase + (size_t)ttv * (size_t)(G4U * BB);
        float yv[8];
        #pragma unroll
        for (int g = 0; g < 4; g++) {
            yv[g]     = __ldcg(Yt + (size_t)(g * UU + u0 + du0) * BB + b);
            yv[4 + g] = __ldcg(Yt + (size_t)(g * UU + u0 + du0 + 4) * BB + b);
        }

        // ---- A build: rows 0-63 = h_hi[b], 64-127 = h_lo[b]
        {
            const __nv_bfloat16* hp = &g_hT[t & 1][0][dir][0][0];
            const size_t split_stride = (size_t)2 * BB * UU;
            #pragma unroll 8
            for (int rep = 0; rep < 32; rep++) {
                int idx = tid + NTHR * rep;
                int row = idx >> 6, c = idx & 63;
                int sp = row >> 6, br = row & 63;
                uint4 v = *(const uint4*)(hp + (size_t)sp * split_stride + (size_t)br * UU + c * 8);
                uint32_t off = (uint32_t)(row * 1024 + ((c ^ (row & 7)) << 4));
                *(uint4*)(smA + off) = v;
            }
        }
        __syncthreads();

        // ---- HMMA mainloop: K=512 in 32 k16 iters
        float D[2][4][4];
        #pragma unroll
        for (int i = 0; i < 2; i++)
            #pragma unroll
            for (int j = 0; j < 4; j++)
                #pragma unroll
                for (int e = 0; e < 4; e++) D[i][j][e] = 0.0f;

        for (int q = 0; q < 8; q++) {
            uint32_t qo = (uint32_t)(q * 128);
            #pragma unroll
            for (int j = 0; j < 4; j++) {
                uint32_t a0[4], a1[4], p0[4], p1[4];
                ldm4(a0, aBase[0] + qo + aSw[0][j]);
                ldm4(a1, aBase[1] + qo + aSw[1][j]);
                ldm4(p0, bBase[0] + qo + bSw[0][j]);
                ldm4(p1, bBase[1] + qo + bSw[1][j]);
                mma16816(D[0][0], a0, p0[0], p0[1]);
                mma16816(D[0][1], a0, p0[2], p0[3]);
                mma16816(D[0][2], a0, p1[0], p1[1]);
                mma16816(D[0][3], a0, p1[2], p1[3]);
                mma16816(D[1][0], a1, p0[0], p0[1]);
                mma16816(D[1][1], a1, p0[2], p0[3]);
                mma16816(D[1][2], a1, p1[0], p1[1]);
                mma16816(D[1][3], a1, p1[2], p1[3]);
            }
        }

        // ---- D -> zbuf (stride ZST=34, 8B-aligned rows)
        {
            int g = lane >> 2, tq = lane & 3;
            float* zw = zbuf + w * (32 * ZST);
            #pragma unroll
            for (int mt = 0; mt < 2; mt++)
                #pragma unroll
                for (int nt = 0; nt < 4; nt++) {
                    int r0_ = mt * 16 + g, cc = nt * 8 + 2 * tq;
                    *(float2*)(zw + r0_ * ZST + cc) = make_float2(D[mt][nt][0], D[mt][nt][1]);
                    *(float2*)(zw + (r0_ + 8) * ZST + cc) = make_float2(D[mt][nt][2], D[mt][nt][3]);
                }
        }
        __syncthreads();

        // ---- cell update: thread (b, du0) handles cells du0 and du0+4
        {
            int lm = b & 31;
            const float* z0 = zbuf + ((b >> 5) * 2 * 32 + lm) * ZST;
            const int o1 = 32 * ZST, o4 = 4 * 32 * ZST, o5 = 5 * 32 * ZST;
            #pragma unroll
            for (int cell = 0; cell < 2; cell++) {
                int du = du0 + 4 * cell;
                float zg4[4];
                #pragma unroll
                for (int g = 0; g < 4; g++) {
                    int n = g * 8 + du;
                    zg4[g] = z0[n] + z0[o1 + n] + z0[o4 + n] + z0[o5 + n] + yv[cell * 4 + g];
                }
                float cn = sigm(zg4[1]) * creg[cell] + sigm(zg4[0]) * tanhf(zg4[2]);
                float hn = sigm(zg4[3]) * tanhf(cn);
                creg[cell] = cn;
                __nv_bfloat16 hi = __float2bfloat16(hn);
                __nv_bfloat16 lo = __float2bfloat16(hn - __bfloat162float(hi));
                hstage[(0 * 64 + b) * 8 + du] = hi;
                hstage[(1 * 64 + b) * 8 + du] = lo;
            }
        }
        __syncthreads();

        // ---- write h' (16B per thread, threads 0-127)
        if (tid < 128) {
            int sp = tid >> 6, br = tid & 63;
            uint4 v = *(const uint4*)(hstage + (sp * 64 + br) * 8);
            __nv_bfloat16* dst = &g_hT[(t + 1) & 1][sp][dir][br][u0];
            *(uint4*)dst = v;
        }

        if (t < TT - 1) gsync(dir);
    }
}

// -------- head --------
__global__ __launch_bounds__(256) void k_head(
    const float* __restrict__ W1, const float* __restrict__ b1,
    const float* __restrict__ W2, const float* __restrict__ b2,
    float* __restrict__ out)
{
    int b = blockIdx.x;
    int tid = threadIdx.x;
    int j = tid & 63, kq = tid >> 6;
    float s = 0.0f;
    for (int k = kq * 256; k < kq * 256 + 256; k++) {
        int dir = k >> 9, u = k & 511;
        float hv = __bfloat162float(g_hT[0][0][dir][b][u]) +
                   __bfloat162float(g_hT[0][1][dir][b][u]);
        s += hv * W1[(size_t)k * 64 + j];
    }
    __shared__ float red[4][64];
    red[kq][j] = s;
    __syncthreads();
    if (tid < 64) {
        float sj = red[0][j] + red[1][j] + red[2][j] + red[3][j] + b1[j];
        red[0][j] = sj * W2[j];
    }
    __syncthreads();
    if (tid == 0) {
        float v = 0.0f;
        #pragma unroll
        for (int q = 0; q < 64; q++) v += red[0][q];
        out[b] = sigm(v + b2[0]);
    }
}

extern "C" void kernel_launch(void* const* d_in, const int* in_sizes, int n_in,
                              void* d_out, int out_size)
{
    const int*   sent = (const int*)  d_in[0];
    const float* emb  = (const float*)d_in[1];
    const float* Wxf  = (const float*)d_in[2];
    const float* Whf  = (const float*)d_in[3];
    const float* bf   = (const float*)d_in[4];
    const float* Wxb  = (const float*)d_in[5];
    const float* Whb  = (const float*)d_in[6];
    const float* bbv  = (const float*)d_in[7];
    const float* W1   = (const float*)d_in[8];
    const float* b1   = (const float*)d_in[9];
    const float* W2   = (const float*)d_in[10];
    const float* b2   = (const float*)d_in[11];
    float* out = (float*)d_out;

    const int smem = 131072 + 65536 + 8 * 32 * ZST * 4;   // 231424 B
    cudaFuncSetAttribute(k_rec, cudaFuncAttributeMaxDynamicSharedMemorySize, smem);

    k_init<<<128, 256>>>();
    k_xw<<<dim3(TT, 64), 128>>>(sent, emb, Wxf, bf, Wxb, bbv);
    k_rec<<<NCTA, NTHR, smem>>>(Whf, Whb);
    k_head<<<64, 256>>>(W1, b1, W2, b2, out);
}

// round 7
// speedup vs baseline: 3.0665x; 1.1120x over previous
#include <cuda_runtime.h>
#include <cuda_bf16.h>
#include <math.h>
#include <stdint.h>

#define TT   512
#define BB   64
#define EE   256
#define UU   512
#define G4U  2048
#define NCTA 128   // 64 per direction
#define NTHR 256
#define ZST  34

// -------- device scratch --------
__device__ __align__(16) float g_Y[(size_t)2 * TT * G4U * BB];   // [dir][t][n][b]
__device__ __align__(16) __nv_bfloat16 g_hT[2][2][2][BB][UU];    // [parity][split][dir][b][u]
__device__ __align__(16) __nv_bfloat16 g_X[TT][2][BB][EE];       // [t][split][b][e]   32 MB
__device__ __align__(16) __nv_bfloat16 g_Wxb[2][2][G4U][EE];     // [dir][split][n][e]  4 MB
__device__ volatile unsigned g_flag[2][64][16];                  // 64B-spaced step flags
__device__ unsigned g_cnt[2][32];
__device__ unsigned g_gen[2][32];

__device__ __forceinline__ float sigm(float x) { return 1.0f / (1.0f + expf(-x)); }

__device__ __forceinline__ uint32_t smem_u32(const void* p) {
    uint32_t a;
    asm("{ .reg .u64 t; cvta.to.shared.u64 t, %1; cvt.u32.u64 %0, t; }" : "=r"(a) : "l"(p));
    return a;
}
__device__ __forceinline__ void ldm4(uint32_t* r, uint32_t addr) {
    asm volatile("ldmatrix.sync.aligned.m8n8.x4.shared.b16 {%0,%1,%2,%3}, [%4];"
                 : "=r"(r[0]), "=r"(r[1]), "=r"(r[2]), "=r"(r[3]) : "r"(addr));
}
__device__ __forceinline__ void mma16816(float* d, const uint32_t* a, uint32_t b0, uint32_t b1) {
    asm volatile("mma.sync.aligned.m16n8k16.row.col.f32.bf16.bf16.f32 "
                 "{%0,%1,%2,%3}, {%4,%5,%6,%7}, {%8,%9}, {%0,%1,%2,%3};"
                 : "+f"(d[0]), "+f"(d[1]), "+f"(d[2]), "+f"(d[3])
                 : "r"(a[0]), "r"(a[1]), "r"(a[2]), "r"(a[3]), "r"(b0), "r"(b1));
}

// -------- prep: Wx -> bf16 hi/lo, n-major --------
__global__ __launch_bounds__(256) void k_prepw(const float* __restrict__ Wxf,
                                               const float* __restrict__ Wxb)
{
    int bid = blockIdx.x;            // 4096 = dir*2048 + n
    int dir = bid >> 11, n = bid & 2047;
    const float* Wx = dir ? Wxb : Wxf;
    int e = threadIdx.x;
    float w = Wx[(size_t)e * G4U + n];
    __nv_bfloat16 hi = __float2bfloat16(w);
    __nv_bfloat16 lo = __float2bfloat16(w - __bfloat162float(hi));
    g_Wxb[dir][0][n][e] = hi;
    g_Wxb[dir][1][n][e] = lo;
}

// -------- prep: embedding gather -> bf16 hi/lo --------
__global__ __launch_bounds__(256) void k_prepx(const int* __restrict__ sent,
                                               const float* __restrict__ emb)
{
    int t = blockIdx.x;              // 512
    int tid = threadIdx.x;
    __shared__ int vrow[64];
    if (tid < 64) vrow[tid] = sent[tid * TT + t];
    __syncthreads();
    for (int b = 0; b < 64; b++) {
        float v = emb[(size_t)vrow[b] * EE + tid];
        __nv_bfloat16 hi = __float2bfloat16(v);
        __nv_bfloat16 lo = __float2bfloat16(v - __bfloat162float(hi));
        g_X[t][0][b][tid] = hi;
        g_X[t][1][b][tid] = lo;
    }
}

// -------- input projection via HMMA: Y[dir][t][n][b] --------
// A[128 x 256] = [x_hi(b); x_lo(b)], B[256 x 256] = [W_hi(128n); W_lo(128n)]
__global__ __launch_bounds__(256) void k_xw2(const float* __restrict__ bf,
                                             const float* __restrict__ bbv)
{
    int bid = blockIdx.x;            // 512 t * 32
    int t = bid >> 5;
    int r5 = bid & 31;
    int dir = r5 >> 4, ntile = r5 & 15;

    extern __shared__ char sm[];
    char* smA = sm;                  // 128 rows x 512B = 64KB
    char* smB = sm + 65536;          // 256 rows x 512B = 128KB
    float* zst = (float*)sm;         // reuse after MMA: [128][129] fp32 (66KB)

    int tid = threadIdx.x, lane = tid & 31, w = tid >> 5;

    // load A (preconverted bf16): rows 0-63 = x_hi, 64-127 = x_lo
    {
        const uint4* Xs = (const uint4*)&g_X[t][0][0][0];
        #pragma unroll
        for (int idx = tid; idx < 4096; idx += 256) {
            int row = idx >> 5, c = idx & 31;
            uint4 v = __ldcg(Xs + idx);
            *(uint4*)(smA + row * 512 + ((c ^ (row & 7)) << 4)) = v;
        }
    }
    // load B: q<128 -> W_hi n=ntile*128+q ; q>=128 -> W_lo
    {
        const uint4* Ws = (const uint4*)&g_Wxb[dir][0][0][0];
        #pragma unroll
        for (int idx = tid; idx < 8192; idx += 256) {
            int q = idx >> 5, c = idx & 31;
            int sp = q >> 7, nl = q & 127;
            uint4 v = __ldcg(Ws + ((size_t)sp * G4U + ntile * 128 + nl) * 32 + c);
            *(uint4*)(smB + q * 512 + ((c ^ (q & 7)) << 4)) = v;
        }
    }
    __syncthreads();

    int mg = w >> 1, ngrp = w & 1;
    uint32_t smA32 = smem_u32(smA), smB32 = smem_u32(smB);

    // A ldmatrix lane mapping (same as verified k_rec)
    uint32_t aBase[2]; int ar7[2]; int dA = (lane >> 4) & 1;
    #pragma unroll
    for (int mt = 0; mt < 2; mt++) {
        int row = mg * 32 + mt * 16 + ((lane >> 3) & 1) * 8 + (lane & 7);
        aBase[mt] = smA32 + row * 512;
        ar7[mt] = row & 7;
    }
    int dB = (lane >> 3) & 1;

    float D[2][8][4];
    #pragma unroll
    for (int i = 0; i < 2; i++)
        #pragma unroll
        for (int j = 0; j < 8; j++)
            #pragma unroll
            for (int e = 0; e < 4; e++) D[i][j][e] = 0.0f;

    #pragma unroll
    for (int p = 0; p < 2; p++) {
        int qb = p * 128 + ngrp * 64;
        uint32_t bBase[4]; int br7[4];
        #pragma unroll
        for (int nt = 0; nt < 4; nt++) {
            int row = qb + nt * 16 + ((lane >> 4) & 1) * 8 + (lane & 7);
            bBase[nt] = smB32 + row * 512;
            br7[nt] = row & 7;
        }
        #pragma unroll 4
        for (int j = 0; j < 16; j++) {
            uint32_t a0[4], a1[4];
            ldm4(a0, aBase[0] + ((((2 * j + dA) ^ ar7[0])) << 4));
            ldm4(a1, aBase[1] + ((((2 * j + dA) ^ ar7[1])) << 4));
            #pragma unroll
            for (int nt = 0; nt < 4; nt++) {
                uint32_t bb[4];
                ldm4(bb, bBase[nt] + ((((2 * j + dB) ^ br7[nt])) << 4));
                mma16816(D[0][2 * nt + 0], a0, bb[0], bb[1]);
                mma16816(D[0][2 * nt + 1], a0, bb[2], bb[3]);
                mma16816(D[1][2 * nt + 0], a1, bb[0], bb[1]);
                mma16816(D[1][2 * nt + 1], a1, bb[2], bb[3]);
            }
        }
    }
    __syncthreads();

    // stage D (hi+lo n-splits already summed in-register) into zst[m][n], pad 129
    {
        int g = lane >> 2, tq = lane & 3;
        #pragma unroll
        for (int mi = 0; mi < 2; mi++)
            #pragma unroll
            for (int nj = 0; nj < 8; nj++) {
                int r = mg * 32 + mi * 16 + g;
                int c = ngrp * 64 + nj * 8 + 2 * tq;
                zst[r * 129 + c]           = D[mi][nj][0];
                zst[r * 129 + c + 1]       = D[mi][nj][1];
                zst[(r + 8) * 129 + c]     = D[mi][nj][2];
                zst[(r + 8) * 129 + c + 1] = D[mi][nj][3];
            }
    }
    __syncthreads();

    // reduce b-split, add bias, transpose-write Y[n][b]
    {
        const float* bias = dir ? bbv : bf;
        float* Y = g_Y + ((size_t)dir * TT + t) * (size_t)(G4U * BB)
                       + (size_t)ntile * 128 * BB;
        #pragma unroll
        for (int rep = 0; rep < 8; rep++) {
            int task = tid + 256 * rep;     // 2048 = 128n x 16 b-quads
            int n = task >> 4, b4 = (task & 15) << 2;
            float bn = bias[ntile * 128 + n];
            float4 o;
            o.x = zst[(b4 + 0) * 129 + n] + zst[(b4 + 64) * 129 + n] + bn;
            o.y = zst[(b4 + 1) * 129 + n] + zst[(b4 + 65) * 129 + n] + bn;
            o.z = zst[(b4 + 2) * 129 + n] + zst[(b4 + 66) * 129 + n] + bn;
            o.w = zst[(b4 + 3) * 129 + n] + zst[(b4 + 67) * 129 + n] + bn;
            *(float4*)(Y + (size_t)n * BB + b4) = o;
        }
    }
}

// -------- flag barrier: per-CTA padded flags, no atomics --------
__device__ __forceinline__ void gsync2(int dir, int cta, unsigned tgt) {
    __threadfence();
    __syncthreads();
    if (threadIdx.x == 0) g_flag[dir][cta][0] = tgt;
    if (threadIdx.x < 64) {
        while (g_flag[dir][threadIdx.x][0] < tgt) {}
    }
    __syncthreads();
}

// -------- persistent HMMA recurrence (unchanged core, new barrier + t0 skip) --------
__global__ __launch_bounds__(NTHR, 1) void k_rec(
    const float* __restrict__ Whf, const float* __restrict__ Whb)
{
    extern __shared__ char dsm[];
    char* smA  = dsm;                        // 131072 B
    char* smB  = dsm + 131072;               // 65536 B
    float* zbuf = (float*)(dsm + 131072 + 65536);
    __nv_bfloat16* hstage = (__nv_bfloat16*)smA;

    int tid = threadIdx.x, lane = tid & 31, w = tid >> 5;
    int dir = blockIdx.x >> 6;
    int cta = blockIdx.x & 63;
    int u0  = cta * 8;
    const float* Wh = dir ? Whb : Whf;

    for (int idx = tid; idx < 64 * 512; idx += NTHR) {
        int n = idx >> 9, k = idx & 511;
        int nl = n & 31;
        float wv = Wh[(size_t)k * G4U + ((nl >> 3) * UU + u0 + (nl & 7))];
        __nv_bfloat16 hi = __float2bfloat16(wv);
        __nv_bfloat16 v = (n < 32) ? hi : __float2bfloat16(wv - __bfloat162float(hi));
        uint32_t off = (uint32_t)(n * 1024 + ((((k >> 3) ^ (n & 7))) << 4) + (k & 7) * 2);
        *(__nv_bfloat16*)(smB + off) = v;
    }
    for (int i = tid; i < 8 * 32 * ZST; i += NTHR) zbuf[i] = 0.0f;

    uint32_t smA32 = smem_u32(smA), smB32 = smem_u32(smB);
    int mg = w >> 1, ng = w & 1;
    uint32_t aBase[2], bBase[2], aSw[2][4], bSw[2][4];
    {
        int dA = (lane >> 4) & 1;
        #pragma unroll
        for (int mt = 0; mt < 2; mt++) {
            int row = mg * 32 + mt * 16 + ((lane >> 3) & 1) * 8 + (lane & 7);
            aBase[mt] = smA32 + row * 1024;
            #pragma unroll
            for (int j = 0; j < 4; j++)
                aSw[mt][j] = (uint32_t)(((2 * j + dA) ^ (row & 7)) << 4);
        }
        int dB = (lane >> 3) & 1;
        #pragma unroll
        for (int nt = 0; nt < 2; nt++) {
            int row = ng * 32 + nt * 16 + ((lane >> 4) & 1) * 8 + (lane & 7);
            bBase[nt] = smB32 + row * 1024;
            #pragma unroll
            for (int j = 0; j < 4; j++)
                bSw[nt][j] = (uint32_t)(((2 * j + dB) ^ (row & 7)) << 4);
        }
    }

    int b = tid & 63, du0 = tid >> 6;
    float creg[2] = {0.0f, 0.0f};
    const float* Ybase = g_Y + (size_t)dir * TT * (size_t)(G4U * BB);
    __syncthreads();

    for (int t = 0; t < TT; t++) {
        int ttv = dir ? (TT - 1 - t) : t;
        const float* Yt = Ybase + (size_t)ttv * (size_t)(G4U * BB);
        float yv[8];
        #pragma unroll
        for (int g = 0; g < 4; g++) {
            yv[g]     = __ldcg(Yt + (size_t)(g * UU + u0 + du0) * BB + b);
            yv[4 + g] = __ldcg(Yt + (size_t)(g * UU + u0 + du0 + 4) * BB + b);
        }

        if (t > 0) {
            {   // A build (L2 loads; flag barrier provides ordering)
                const __nv_bfloat16* hp = &g_hT[t & 1][0][dir][0][0];
                const size_t split_stride = (size_t)2 * BB * UU;
                #pragma unroll 8
                for (int rep = 0; rep < 32; rep++) {
                    int idx = tid + NTHR * rep;
                    int row = idx >> 6, c = idx & 63;
                    int sp = row >> 6, br = row & 63;
                    uint4 v = __ldcg((const uint4*)(hp + (size_t)sp * split_stride
                                                       + (size_t)br * UU + c * 8));
                    *(uint4*)(smA + row * 1024 + ((c ^ (row & 7)) << 4)) = v;
                }
            }
            __syncthreads();

            float D[2][4][4];
            #pragma unroll
            for (int i = 0; i < 2; i++)
                #pragma unroll
                for (int j = 0; j < 4; j++)
                    #pragma unroll
                    for (int e = 0; e < 4; e++) D[i][j][e] = 0.0f;

            for (int q = 0; q < 8; q++) {
                uint32_t qo = (uint32_t)(q * 128);
                #pragma unroll
                for (int j = 0; j < 4; j++) {
                    uint32_t a0[4], a1[4], p0[4], p1[4];
                    ldm4(a0, aBase[0] + qo + aSw[0][j]);
                    ldm4(a1, aBase[1] + qo + aSw[1][j]);
                    ldm4(p0, bBase[0] + qo + bSw[0][j]);
                    ldm4(p1, bBase[1] + qo + bSw[1][j]);
                    mma16816(D[0][0], a0, p0[0], p0[1]);
                    mma16816(D[0][1], a0, p0[2], p0[3]);
                    mma16816(D[0][2], a0, p1[0], p1[1]);
                    mma16816(D[0][3], a0, p1[2], p1[3]);
                    mma16816(D[1][0], a1, p0[0], p0[1]);
                    mma16816(D[1][1], a1, p0[2], p0[3]);
                    mma16816(D[1][2], a1, p1[0], p1[1]);
                    mma16816(D[1][3], a1, p1[2], p1[3]);
                }
            }

            {
                int g = lane >> 2, tq = lane & 3;
                float* zw = zbuf + w * (32 * ZST);
                #pragma unroll
                for (int mt = 0; mt < 2; mt++)
                    #pragma unroll
                    for (int nt = 0; nt < 4; nt++) {
                        int r0_ = mt * 16 + g, cc = nt * 8 + 2 * tq;
                        *(float2*)(zw + r0_ * ZST + cc) = make_float2(D[mt][nt][0], D[mt][nt][1]);
                        *(float2*)(zw + (r0_ + 8) * ZST + cc) = make_float2(D[mt][nt][2], D[mt][nt][3]);
                    }
            }
        }
        __syncthreads();

        {   // cell update
            int lm = b & 31;
            const float* z0 = zbuf + ((b >> 5) * 2 * 32 + lm) * ZST;
            const int o1 = 32 * ZST, o4 = 4 * 32 * ZST, o5 = 5 * 32 * ZST;
            #pragma unroll
            for (int cell = 0; cell < 2; cell++) {
                int du = du0 + 4 * cell;
                float zg4[4];
                #pragma unroll
                for (int g = 0; g < 4; g++) {
                    int n = g * 8 + du;
                    zg4[g] = z0[n] + z0[o1 + n] + z0[o4 + n] + z0[o5 + n] + yv[cell * 4 + g];
                }
                float cn = sigm(zg4[1]) * creg[cell] + sigm(zg4[0]) * tanhf(zg4[2]);
                float hn = sigm(zg4[3]) * tanhf(cn);
                creg[cell] = cn;
                __nv_bfloat16 hi = __float2bfloat16(hn);
                __nv_bfloat16 lo = __float2bfloat16(hn - __bfloat162float(hi));
                hstage[(0 * 64 + b) * 8 + du] = hi;
                hstage[(1 * 64 + b) * 8 + du] = lo;
            }
        }
        __syncthreads();

        if (tid < 128) {
            int sp = tid >> 6, br = tid & 63;
            uint4 v = *(const uint4*)(hstage + (sp * 64 + br) * 8);
            *(uint4*)(&g_hT[(t + 1) & 1][sp][dir][br][u0]) = v;
        }

        if (t < TT - 1) gsync2(dir, cta, (unsigned)(t + 1));
    }

    // final all-arrive barrier (atomic, once), then reset flags for next replay
    __threadfence();
    __syncthreads();
    if (tid == 0) {
        volatile unsigned* gen = &g_gen[dir][0];
        unsigned g = *gen;
        unsigned a = atomicAdd(&g_cnt[dir][0], 1u);
        if (a == 63) {
            g_cnt[dir][0] = 0;
            __threadfence();
            *gen = g + 1;
        } else {
            while (*gen == g) {}
        }
        g_flag[dir][cta][0] = 0;
    }
}

// -------- head --------
__global__ __launch_bounds__(256) void k_head(
    const float* __restrict__ W1, const float* __restrict__ b1,
    const float* __restrict__ W2, const float* __restrict__ b2,
    float* __restrict__ out)
{
    int b = blockIdx.x;
    int tid = threadIdx.x;
    int j = tid & 63, kq = tid >> 6;
    float s = 0.0f;
    for (int k = kq * 256; k < kq * 256 + 256; k++) {
        int dir = k >> 9, u = k & 511;
        float hv = __bfloat162float(g_hT[0][0][dir][b][u]) +
                   __bfloat162float(g_hT[0][1][dir][b][u]);
        s += hv * W1[(size_t)k * 64 + j];
    }
    __shared__ float red[4][64];
    red[kq][j] = s;
    __syncthreads();
    if (tid < 64) {
        float sj = red[0][j] + red[1][j] + red[2][j] + red[3][j] + b1[j];
        red[0][j] = sj * W2[j];
    }
    __syncthreads();
    if (tid == 0) {
        float v = 0.0f;
        #pragma unroll
        for (int q = 0; q < 64; q++) v += red[0][q];
        out[b] = sigm(v + b2[0]);
    }
}

extern "C" void kernel_launch(void* const* d_in, const int* in_sizes, int n_in,
                              void* d_out, int out_size)
{
    const int*   sent = (const int*)  d_in[0];
    const float* emb  = (const float*)d_in[1];
    const float* Wxf  = (const float*)d_in[2];
    const float* Whf  = (const float*)d_in[3];
    const float* bf   = (const float*)d_in[4];
    const float* Wxb  = (const float*)d_in[5];
    const float* Whb  = (const float*)d_in[6];
    const float* bbv  = (const float*)d_in[7];
    const float* W1   = (const float*)d_in[8];
    const float* b1   = (const float*)d_in[9];
    const float* W2   = (const float*)d_in[10];
    const float* b2   = (const float*)d_in[11];
    float* out = (float*)d_out;

    const int smem_rec = 131072 + 65536 + 8 * 32 * ZST * 4;   // 231424 B
    const int smem_xw  = 65536 + 131072;                      // 196608 B
    cudaFuncSetAttribute(k_rec, cudaFuncAttributeMaxDynamicSharedMemorySize, smem_rec);
    cudaFuncSetAttribute(k_xw2, cudaFuncAttributeMaxDynamicSharedMemorySize, smem_xw);

    k_prepw<<<4096, 256>>>(Wxf, Wxb);
    k_prepx<<<512, 256>>>(sent, emb);
    k_xw2<<<512 * 32, 256, smem_xw>>>(bf, bbv);
    k_rec<<<NCTA, NTHR, smem_rec>>>(Whf, Whb);
    k_head<<<64, 256>>>(W1, b1, W2, b2, out);
}